// round 9
// baseline (speedup 1.0000x reference)
#include <cuda_runtime.h>
#include <cuda_fp16.h>
#include <math.h>
#include <stdint.h>

// ---------------------------------------------------------------------------
// MoE dispatch/combine via mma.sync HMMA (sm_100 target):
//   out[m] = sum_k w[m,k] * silu(x[m] @ W[e(m,k)] + b[e(m,k)])
// R9: R6 synchronous register-prefetch GEMM (proven) + upfront fp16 X convert
// (halves gathered-A traffic, simplifies the mainloop). No cp.async — that
// construct kills the container on this stack (R7/R8 evidence).
// ---------------------------------------------------------------------------

#define N_NODE   8192
#define N_EDGE   65536
#define N_ANGLE  131072
#define ND       128
#define NSYM     768
#define EINFO    320
#define ADIM     128
#define DO_NODE  128
#define DO_EDGE  192
#define DO_ANGLE 96

#define CAPN 4096
#define CAPE 32768
#define CAPA 65536

#define OUT_M1    ((size_t)0)
#define OUT_M2    ((size_t)N_NODE * ND)
#define OUT_EDGE  (OUT_M2 + (size_t)N_NODE * ND)
#define OUT_ANGLE (OUT_EDGE + (size_t)N_EDGE * DO_EDGE)

// ---------------- device scratch -------------------------------------------
__device__ int   g_cnt[24];
__device__ __align__(16) int   g_rows_node [8 * CAPN];
__device__ __align__(16) float g_w_node    [8 * CAPN];
__device__ __align__(16) int   g_rows_edge [8 * CAPE];
__device__ __align__(16) float g_w_edge    [8 * CAPE];
__device__ __align__(16) int   g_rows_angle[8 * CAPA];
__device__ __align__(16) float g_w_angle   [8 * CAPA];
__device__ __align__(16) int   g_pos_node [2 * N_NODE];
__device__ __align__(16) int   g_pos_edge [2 * N_EDGE];
__device__ __align__(16) int   g_pos_angle[2 * N_ANGLE];

// fp16 inputs
__device__ __align__(16) __half g_xm1h[(size_t)N_NODE * ND];
__device__ __align__(16) __half g_xm2h[(size_t)N_NODE * NSYM];
__device__ __align__(16) __half g_xeh [(size_t)N_EDGE * EINFO];
__device__ __align__(16) __half g_xah [(size_t)N_ANGLE * ADIM];
// transposed weights: [E][DOUT][DIN] fp16 (K-major rows)
__device__ __align__(16) __half g_w1t[(size_t)8 * DO_NODE  * ND];
__device__ __align__(16) __half g_w2t[(size_t)8 * DO_NODE  * NSYM];
__device__ __align__(16) __half g_wet[(size_t)8 * DO_EDGE  * EINFO];
__device__ __align__(16) __half g_wat[(size_t)8 * DO_ANGLE * ADIM];
// per-slot GEMM outputs (fp16)
__device__ __align__(16) __half g_s_m1[(size_t)8 * CAPN * DO_NODE];
__device__ __align__(16) __half g_s_m2[(size_t)8 * CAPN * DO_NODE];
__device__ __align__(16) __half g_s_e [(size_t)8 * CAPE * DO_EDGE];
__device__ __align__(16) __half g_s_a [(size_t)8 * CAPA * DO_ANGLE];

// ---------------- helpers ---------------------------------------------------
__device__ __forceinline__ uint32_t smem_u32(const void* p) {
    uint32_t a;
    asm("{ .reg .u64 t; cvta.to.shared.u64 t, %1; cvt.u32.u64 %0, t; }"
        : "=r"(a) : "l"(p));
    return a;
}

#define LDMATRIX_X4(r0, r1, r2, r3, addr) \
    asm volatile("ldmatrix.sync.aligned.m8n8.x4.shared.b16 {%0,%1,%2,%3}, [%4];" \
                 : "=r"(r0), "=r"(r1), "=r"(r2), "=r"(r3) : "r"(addr))

#define LDMATRIX_X2(r0, r1, addr) \
    asm volatile("ldmatrix.sync.aligned.m8n8.x2.shared.b16 {%0,%1}, [%2];" \
                 : "=r"(r0), "=r"(r1) : "r"(addr))

#define MMA_16816(c, a, b) \
    asm volatile("mma.sync.aligned.m16n8k16.row.col.f32.f16.f16.f32 " \
                 "{%0,%1,%2,%3}, {%4,%5,%6,%7}, {%8,%9}, {%0,%1,%2,%3};" \
                 : "+f"((c)[0]), "+f"((c)[1]), "+f"((c)[2]), "+f"((c)[3]) \
                 : "r"((a)[0]), "r"((a)[1]), "r"((a)[2]), "r"((a)[3]), \
                   "r"((b)[0]), "r"((b)[1]))

#define STS128(addr, v0, v1, v2, v3) \
    asm volatile("st.shared.v4.b32 [%0], {%1,%2,%3,%4};" \
                 :: "r"(addr), "r"(v0), "r"(v1), "r"(v2), "r"(v3) : "memory")

// ---------------- init ------------------------------------------------------
__global__ void init_kernel() {
    if (threadIdx.x < 24) g_cnt[threadIdx.x] = 0;
}

// ---------------- fp32 -> fp16 input converts --------------------------------
template<int WHICH>
__global__ void cvt_kernel(const float4* __restrict__ x, int n4) {
    __half* dst;
    if      (WHICH == 0) dst = g_xm1h;
    else if (WHICH == 1) dst = g_xm2h;
    else if (WHICH == 2) dst = g_xeh;
    else                 dst = g_xah;
    int i = blockIdx.x * 256 + threadIdx.x;
    if (i >= n4) return;
    float4 v = x[i];
    __half2 a = __floats2half2_rn(v.x, v.y);
    __half2 b = __floats2half2_rn(v.z, v.w);
    uint2 o;
    o.x = *reinterpret_cast<unsigned int*>(&a);
    o.y = *reinterpret_cast<unsigned int*>(&b);
    reinterpret_cast<uint2*>(dst)[i] = o;
}

// ---------------- coalesced transpose+convert weights -----------------------
template<int WHICH>
__global__ void wcvt_kernel(const float* __restrict__ W) {
    constexpr int DIN  = (WHICH == 0) ? ND : (WHICH == 1) ? NSYM : (WHICH == 2) ? EINFO : ADIM;
    constexpr int DOUT = (WHICH <= 1) ? DO_NODE : (WHICH == 2) ? DO_EDGE : DO_ANGLE;
    __half* Wt;
    if      (WHICH == 0) Wt = g_w1t;
    else if (WHICH == 1) Wt = g_w2t;
    else if (WHICH == 2) Wt = g_wet;
    else                 Wt = g_wat;

    __shared__ float t[32][33];
    const int e  = blockIdx.y;
    const int nk = DIN / 32;
    const int k0 = (blockIdx.x % nk) * 32;
    const int n0 = (blockIdx.x / nk) * 32;
    const int tx = threadIdx.x, ty = threadIdx.y;
#pragma unroll
    for (int i = 0; i < 4; ++i)
        t[ty + 8 * i][tx] = W[((size_t)e * DIN + k0 + ty + 8 * i) * DOUT + n0 + tx];
    __syncthreads();
#pragma unroll
    for (int i = 0; i < 4; ++i)
        Wt[((size_t)e * DOUT + n0 + ty + 8 * i) * DIN + k0 + tx] =
            __float2half_rn(t[tx][ty + 8 * i]);
}

// ---------------- routing ---------------------------------------------------
template<int WHICH>
__global__ void route_kernel(const int* __restrict__ idx,
                             const float* __restrict__ wts,
                             const int* __restrict__ map, int M) {
    int* cnt = g_cnt + WHICH * 8;
    int* rowlist; float* wlist; int* pos; int cap;
    if      (WHICH == 0) { rowlist = g_rows_node;  wlist = g_w_node;  pos = g_pos_node;  cap = CAPN; }
    else if (WHICH == 1) { rowlist = g_rows_edge;  wlist = g_w_edge;  pos = g_pos_edge;  cap = CAPE; }
    else                 { rowlist = g_rows_angle; wlist = g_w_angle; pos = g_pos_angle; cap = CAPA; }

    int i = blockIdx.x * blockDim.x + threadIdx.x;
    if (i >= M) return;
    int src = (WHICH == 0) ? i : map[i];
    int lane = threadIdx.x & 31;

#pragma unroll
    for (int k = 0; k < 2; ++k) {
        int   e = idx[2 * src + k];
        float w = wts[2 * src + k];
        unsigned mask = __match_any_sync(0xffffffffu, e);
        int leader = __ffs(mask) - 1;
        int rank   = __popc(mask & ((1u << lane) - 1u));
        int base = 0;
        if (lane == leader) base = atomicAdd(&cnt[e], __popc(mask));
        base = __shfl_sync(mask, base, leader);
        int p = base + rank;
        if (p > cap - 1) p = cap - 1;     // statistically impossible; keep in bounds
        int flat = e * cap + p;
        rowlist[flat] = i;
        wlist[flat]   = w;
        pos[2 * i + k] = flat;
    }
}

// ---------------- grouped HMMA GEMM -----------------------------------------
// 64 rows x full DOUT per CTA, 256 threads = 8 warps (2m x 4n), BK=32.
// K-major smem, 80B rows (conflict-free ldmatrix). A is fp16 (pre-converted):
// one 16B LDG + one STS128 per thread per chunk. Register prefetch overlaps
// the next chunk's LDGs with the current chunk's MMAs.
template<int WHICH>
__global__ void __launch_bounds__(256)
moe_gemm_mma(const float* __restrict__ Bias) {
    constexpr int DIN  = (WHICH == 0) ? ND : (WHICH == 1) ? NSYM : (WHICH == 2) ? EINFO : ADIM;
    constexpr int DOUT = (WHICH <= 1) ? DO_NODE : (WHICH == 2) ? DO_EDGE : DO_ANGLE;
    constexpr int CAP  = (WHICH <= 1) ? CAPN : (WHICH == 2) ? CAPE : CAPA;
    constexpr int WN   = DOUT / 4;       // cols per warp band
    constexpr int FN   = WN / 8;         // n fragments per warp (4/6/3)
    constexpr int NCH  = DIN / 32;

    const __half* Xh; const __half* Wt; __half* Scr;
    const int* rowlist; const float* wlist;
    if (WHICH == 0) { Xh = g_xm1h; Wt = g_w1t; Scr = g_s_m1; rowlist = g_rows_node;  wlist = g_w_node;  }
    if (WHICH == 1) { Xh = g_xm2h; Wt = g_w2t; Scr = g_s_m2; rowlist = g_rows_node;  wlist = g_w_node;  }
    if (WHICH == 2) { Xh = g_xeh;  Wt = g_wet; Scr = g_s_e;  rowlist = g_rows_edge;  wlist = g_w_edge;  }
    if (WHICH == 3) { Xh = g_xah;  Wt = g_wat; Scr = g_s_a;  rowlist = g_rows_angle; wlist = g_w_angle; }
    const int which_r = (WHICH <= 1) ? 0 : (WHICH - 1);

    const int e = blockIdx.y;
    int count = min(g_cnt[which_r * 8 + e], CAP);
    const int m0 = blockIdx.x * 64;
    if (m0 >= count) return;

    __shared__ __align__(16) __half As[64 * 40];     // 64 rows x 80B
    __shared__ __align__(16) __half Bs[DOUT * 40];   // DOUT rows x 80B
    __shared__ int   srow[64];
    __shared__ float swt[64];

    const int tid  = threadIdx.x;
    const int wid  = tid >> 5;
    const int lane = tid & 31;
    const int warp_m = wid & 1;        // 0..1 -> 32-row band
    const int warp_n = wid >> 1;       // 0..3 -> WN-col band

    if (tid < 64) {
        int m = m0 + tid;
        if (m < count) { srow[tid] = rowlist[e * CAP + m]; swt[tid] = wlist[e * CAP + m]; }
        else           { srow[tid] = rowlist[e * CAP];     swt[tid] = 0.f; }
    }
    __syncthreads();

    // A fill: 4 threads per row, one 16B chunk (8 halfs) each per 32-chunk
    const int arow = tid >> 2;          // 0..63
    const int aseg = tid & 3;           // 8-half segment
    const __half* aptr = Xh + (size_t)srow[arow] * DIN + aseg * 8;
    const bool bval = tid < DOUT;
    const __half* bptr = Wt + ((size_t)e * DOUT + (bval ? tid : 0)) * DIN;

    const uint32_t As_u = smem_u32(As), Bs_u = smem_u32(Bs);
    const uint32_t a_st = As_u + (uint32_t)arow * 80u + (uint32_t)aseg * 16u;
    const uint32_t b_st = Bs_u + (uint32_t)tid * 80u;
    const uint32_t a_ld = As_u + (uint32_t)(warp_m * 32 + (lane & 15)) * 80u
                          + (uint32_t)(lane >> 4) * 16u;
    const uint32_t b_ld = Bs_u + (uint32_t)(warp_n * WN + (lane & 7)) * 80u
                          + (uint32_t)((lane >> 3) & 1) * 16u;

    float acc[2][FN][4];
#pragma unroll
    for (int i = 0; i < 2; ++i)
#pragma unroll
        for (int j = 0; j < FN; ++j)
#pragma unroll
            for (int q = 0; q < 4; ++q) acc[i][j][q] = 0.f;

    uint4 ar;
    uint4 br[4];

    // prologue prefetch (chunk 0)
    ar = *reinterpret_cast<const uint4*>(aptr);
    if (bval) {
#pragma unroll
        for (int j = 0; j < 4; ++j) br[j] = *reinterpret_cast<const uint4*>(bptr + j * 8);
    }

    for (int c = 0; c < NCH; ++c) {
        __syncthreads();    // previous chunk's ldmatrix reads complete
        STS128(a_st, ar.x, ar.y, ar.z, ar.w);
        if (bval) {
#pragma unroll
            for (int j = 0; j < 4; ++j)
                STS128(b_st + (uint32_t)j * 16u, br[j].x, br[j].y, br[j].z, br[j].w);
        }
        __syncthreads();
        // prefetch next chunk (LDG latency overlaps MMA below)
        if (c + 1 < NCH) {
            ar = *reinterpret_cast<const uint4*>(aptr + (c + 1) * 32);
            if (bval) {
#pragma unroll
                for (int j = 0; j < 4; ++j)
                    br[j] = *reinterpret_cast<const uint4*>(bptr + (c + 1) * 32 + j * 8);
            }
        }
#pragma unroll
        for (int kk = 0; kk < 2; ++kk) {
            uint32_t a[2][4], b[FN][2];
#pragma unroll
            for (int fm = 0; fm < 2; ++fm)
                LDMATRIX_X4(a[fm][0], a[fm][1], a[fm][2], a[fm][3],
                            a_ld + (uint32_t)fm * 16u * 80u + (uint32_t)kk * 32u);
#pragma unroll
            for (int fn = 0; fn < FN; ++fn)
                LDMATRIX_X2(b[fn][0], b[fn][1],
                            b_ld + (uint32_t)fn * 8u * 80u + (uint32_t)kk * 32u);
#pragma unroll
            for (int fm = 0; fm < 2; ++fm)
#pragma unroll
                for (int fn = 0; fn < FN; ++fn)
                    MMA_16816(acc[fm][fn], a[fm], b[fn]);
        }
    }

    // epilogue: bias + silu + topk-weight -> fp16 slot scratch (half2 stores)
    const int qrow = lane >> 2;
    const int qcol = (lane & 3) * 2;
    const float* be = Bias + e * DOUT;
#pragma unroll
    for (int fm = 0; fm < 2; ++fm) {
#pragma unroll
        for (int hf = 0; hf < 2; ++hf) {
            int rloc = warp_m * 32 + fm * 16 + hf * 8 + qrow;
            int m = m0 + rloc;
            if (m >= count) continue;
            float wt = swt[rloc];
            __half* orow = Scr + ((size_t)e * CAP + m) * DOUT;
#pragma unroll
            for (int fn = 0; fn < FN; ++fn) {
                int col = warp_n * WN + fn * 8 + qcol;
                float h0 = acc[fm][fn][hf * 2 + 0] + be[col];
                float h1 = acc[fm][fn][hf * 2 + 1] + be[col + 1];
                float s0 = wt * (h0 / (1.f + __expf(-h0)));
                float s1 = wt * (h1 / (1.f + __expf(-h1)));
                *reinterpret_cast<__half2*>(orow + col) = __floats2half2_rn(s0, s1);
            }
        }
    }
}

// ---------------- combine: out[r] = scratch[pos0] + scratch[pos1] -----------
template<int WHICH>
__global__ void combine_kernel(float* __restrict__ out) {
    constexpr int D  = (WHICH <= 1) ? DO_NODE : (WHICH == 2) ? DO_EDGE : DO_ANGLE;
    constexpr int D4 = D / 4;
    constexpr int M  = (WHICH <= 1) ? N_NODE : (WHICH == 2) ? N_EDGE : N_ANGLE;
    const int* pos; const __half* s;
    if (WHICH == 0) { pos = g_pos_node;  s = g_s_m1; }
    if (WHICH == 1) { pos = g_pos_node;  s = g_s_m2; }
    if (WHICH == 2) { pos = g_pos_edge;  s = g_s_e;  }
    if (WHICH == 3) { pos = g_pos_angle; s = g_s_a;  }

    int idx = blockIdx.x * 256 + threadIdx.x;
    if (idx >= M * D4) return;
    int r = idx / D4;
    int q = idx - r * D4;
    int p0 = pos[2 * r], p1 = pos[2 * r + 1];
    uint2 va = *reinterpret_cast<const uint2*>(s + (size_t)p0 * D + q * 4);
    uint2 vb = *reinterpret_cast<const uint2*>(s + (size_t)p1 * D + q * 4);
    float2 a0 = __half22float2(*reinterpret_cast<__half2*>(&va.x));
    float2 a1 = __half22float2(*reinterpret_cast<__half2*>(&va.y));
    float2 b0 = __half22float2(*reinterpret_cast<__half2*>(&vb.x));
    float2 b1 = __half22float2(*reinterpret_cast<__half2*>(&vb.y));
    reinterpret_cast<float4*>(out)[idx] =
        make_float4(a0.x + b0.x, a0.y + b0.y, a1.x + b1.x, a1.y + b1.y);
}

// ---------------- launch ----------------------------------------------------
extern "C" void kernel_launch(void* const* d_in, const int* in_sizes, int n_in,
                              void* d_out, int out_size) {
    const float* x_m1 = (const float*)d_in[0];
    const float* x_m2 = (const float*)d_in[1];
    const float* x_e  = (const float*)d_in[2];
    const float* x_a  = (const float*)d_in[3];
    const float* nw   = (const float*)d_in[4];
    const int*   ni   = (const int*)  d_in[5];
    const float* ewn  = (const float*)d_in[6];
    const int*   ein  = (const int*)  d_in[7];
    const float* awn  = (const float*)d_in[8];
    const int*   ain  = (const int*)  d_in[9];
    const int*   n2e  = (const int*)  d_in[10];
    const int*   n2a  = (const int*)  d_in[11];
    const float* W1 = (const float*)d_in[12];
    const float* b1 = (const float*)d_in[13];
    const float* W2 = (const float*)d_in[14];
    const float* b2 = (const float*)d_in[15];
    const float* We = (const float*)d_in[16];
    const float* be = (const float*)d_in[17];
    const float* Wa = (const float*)d_in[18];
    const float* ba = (const float*)d_in[19];
    float* out = (float*)d_out;
    (void)in_sizes; (void)n_in; (void)out_size;

    // 1) counters, input converts, weight transpose/convert
    init_kernel<<<1, 32>>>();
    cvt_kernel<0><<<(N_NODE  * ND    / 4 + 255) / 256, 256>>>((const float4*)x_m1, N_NODE  * ND    / 4);
    cvt_kernel<1><<<(N_NODE  * NSYM  / 4 + 255) / 256, 256>>>((const float4*)x_m2, N_NODE  * NSYM  / 4);
    cvt_kernel<2><<<(N_EDGE  * EINFO / 4 + 255) / 256, 256>>>((const float4*)x_e,  N_EDGE  * EINFO / 4);
    cvt_kernel<3><<<(N_ANGLE * ADIM  / 4 + 255) / 256, 256>>>((const float4*)x_a,  N_ANGLE * ADIM  / 4);
    wcvt_kernel<0><<<dim3((ND   / 32) * (DO_NODE  / 32), 8), dim3(32, 8)>>>(W1);
    wcvt_kernel<1><<<dim3((NSYM / 32) * (DO_NODE  / 32), 8), dim3(32, 8)>>>(W2);
    wcvt_kernel<2><<<dim3((EINFO/ 32) * (DO_EDGE  / 32), 8), dim3(32, 8)>>>(We);
    wcvt_kernel<3><<<dim3((ADIM / 32) * (DO_ANGLE / 32), 8), dim3(32, 8)>>>(Wa);

    // 2) routing
    route_kernel<0><<<N_NODE  / 256, 256>>>(ni,  nw,  nullptr, N_NODE);
    route_kernel<1><<<N_EDGE  / 256, 256>>>(ein, ewn, n2e,     N_EDGE);
    route_kernel<2><<<N_ANGLE / 256, 256>>>(ain, awn, n2a,     N_ANGLE);

    // 3) grouped HMMA GEMMs (BM=64 x full DOUT; y = expert), largest first
    moe_gemm_mma<3><<<dim3(CAPA / 64, 8), 256>>>(ba);
    moe_gemm_mma<2><<<dim3(CAPE / 64, 8), 256>>>(be);
    moe_gemm_mma<1><<<dim3(CAPN / 64, 8), 256>>>(b2);
    moe_gemm_mma<0><<<dim3(CAPN / 64, 8), 256>>>(b1);

    // 4) combine the two expert slots per row
    combine_kernel<0><<<(N_NODE  * (DO_NODE  / 4) + 255) / 256, 256>>>(out + OUT_M1);
    combine_kernel<1><<<(N_NODE  * (DO_NODE  / 4) + 255) / 256, 256>>>(out + OUT_M2);
    combine_kernel<2><<<(N_EDGE  * (DO_EDGE  / 4) + 255) / 256, 256>>>(out + OUT_EDGE);
    combine_kernel<3><<<(N_ANGLE * (DO_ANGLE / 4) + 255) / 256, 256>>>(out + OUT_ANGLE);
}

// round 10
// speedup vs baseline: 1.1574x; 1.1574x over previous
#include <cuda_runtime.h>
#include <cuda_fp16.h>
#include <math.h>
#include <stdint.h>

// ---------------------------------------------------------------------------
// MoE dispatch/combine via mma.sync HMMA (sm_100 target):
//   out[m] = sum_k w[m,k] * silu(x[m] @ W[e(m,k)] + b[e(m,k)])
// R10: R6 GEMM (proven 386us) with direct-atomic epilogue into pre-zeroed
// fp32 output (R1-proven construct) -- removes the fp16 scratch round-trip
// and the 4 combine kernels entirely. Output (109MB) is L2-resident.
// ---------------------------------------------------------------------------

#define N_NODE   8192
#define N_EDGE   65536
#define N_ANGLE  131072
#define ND       128
#define NSYM     768
#define EINFO    320
#define ADIM     128
#define DO_NODE  128
#define DO_EDGE  192
#define DO_ANGLE 96

#define CAPN 4096
#define CAPE 32768
#define CAPA 65536

#define OUT_M1    ((size_t)0)
#define OUT_M2    ((size_t)N_NODE * ND)
#define OUT_EDGE  (OUT_M2 + (size_t)N_NODE * ND)
#define OUT_ANGLE (OUT_EDGE + (size_t)N_EDGE * DO_EDGE)
#define OUT_TOTAL (OUT_ANGLE + (size_t)N_ANGLE * DO_ANGLE)   // 27,262,976 floats

// ---------------- device scratch -------------------------------------------
__device__ int   g_cnt[24];
__device__ __align__(16) int   g_rows_node [8 * CAPN];
__device__ __align__(16) float g_w_node    [8 * CAPN];
__device__ __align__(16) int   g_rows_edge [8 * CAPE];
__device__ __align__(16) float g_w_edge    [8 * CAPE];
__device__ __align__(16) int   g_rows_angle[8 * CAPA];
__device__ __align__(16) float g_w_angle   [8 * CAPA];

// transposed weights: [E][DOUT][DIN] fp16 (K-major rows)
__device__ __align__(16) __half g_w1t[(size_t)8 * DO_NODE  * ND];
__device__ __align__(16) __half g_w2t[(size_t)8 * DO_NODE  * NSYM];
__device__ __align__(16) __half g_wet[(size_t)8 * DO_EDGE  * EINFO];
__device__ __align__(16) __half g_wat[(size_t)8 * DO_ANGLE * ADIM];

// ---------------- helpers ---------------------------------------------------
__device__ __forceinline__ uint32_t smem_u32(const void* p) {
    uint32_t a;
    asm("{ .reg .u64 t; cvta.to.shared.u64 t, %1; cvt.u32.u64 %0, t; }"
        : "=r"(a) : "l"(p));
    return a;
}

__device__ __forceinline__ uint32_t h2b(__half2 h) {
    return *reinterpret_cast<uint32_t*>(&h);
}

#define LDMATRIX_X4(r0, r1, r2, r3, addr) \
    asm volatile("ldmatrix.sync.aligned.m8n8.x4.shared.b16 {%0,%1,%2,%3}, [%4];" \
                 : "=r"(r0), "=r"(r1), "=r"(r2), "=r"(r3) : "r"(addr))

#define LDMATRIX_X2(r0, r1, addr) \
    asm volatile("ldmatrix.sync.aligned.m8n8.x2.shared.b16 {%0,%1}, [%2];" \
                 : "=r"(r0), "=r"(r1) : "r"(addr))

#define MMA_16816(c, a, b) \
    asm volatile("mma.sync.aligned.m16n8k16.row.col.f32.f16.f16.f32 " \
                 "{%0,%1,%2,%3}, {%4,%5,%6,%7}, {%8,%9}, {%0,%1,%2,%3};" \
                 : "+f"((c)[0]), "+f"((c)[1]), "+f"((c)[2]), "+f"((c)[3]) \
                 : "r"((a)[0]), "r"((a)[1]), "r"((a)[2]), "r"((a)[3]), \
                   "r"((b)[0]), "r"((b)[1]))

#define STS128(addr, v0, v1, v2, v3) \
    asm volatile("st.shared.v4.b32 [%0], {%1,%2,%3,%4};" \
                 :: "r"(addr), "r"(v0), "r"(v1), "r"(v2), "r"(v3) : "memory")

// ---------------- init: zero outputs + counters ------------------------------
__global__ void init_kernel(float* __restrict__ out, int n4) {
    int i = blockIdx.x * blockDim.x + threadIdx.x;
    if (i < n4) reinterpret_cast<float4*>(out)[i] = make_float4(0.f, 0.f, 0.f, 0.f);
    if (i < 24) g_cnt[i] = 0;
}

// ---------------- coalesced transpose+convert weights -----------------------
template<int WHICH>
__global__ void wcvt_kernel(const float* __restrict__ W) {
    constexpr int DIN  = (WHICH == 0) ? ND : (WHICH == 1) ? NSYM : (WHICH == 2) ? EINFO : ADIM;
    constexpr int DOUT = (WHICH <= 1) ? DO_NODE : (WHICH == 2) ? DO_EDGE : DO_ANGLE;
    __half* Wt;
    if      (WHICH == 0) Wt = g_w1t;
    else if (WHICH == 1) Wt = g_w2t;
    else if (WHICH == 2) Wt = g_wet;
    else                 Wt = g_wat;

    __shared__ float t[32][33];
    const int e  = blockIdx.y;
    const int nk = DIN / 32;
    const int k0 = (blockIdx.x % nk) * 32;
    const int n0 = (blockIdx.x / nk) * 32;
    const int tx = threadIdx.x, ty = threadIdx.y;
#pragma unroll
    for (int i = 0; i < 4; ++i)
        t[ty + 8 * i][tx] = W[((size_t)e * DIN + k0 + ty + 8 * i) * DOUT + n0 + tx];
    __syncthreads();
#pragma unroll
    for (int i = 0; i < 4; ++i)
        Wt[((size_t)e * DOUT + n0 + ty + 8 * i) * DIN + k0 + tx] =
            __float2half_rn(t[tx][ty + 8 * i]);
}

// ---------------- routing ---------------------------------------------------
template<int WHICH>
__global__ void route_kernel(const int* __restrict__ idx,
                             const float* __restrict__ wts,
                             const int* __restrict__ map, int M) {
    int* cnt = g_cnt + WHICH * 8;
    int* rowlist; float* wlist; int cap;
    if      (WHICH == 0) { rowlist = g_rows_node;  wlist = g_w_node;  cap = CAPN; }
    else if (WHICH == 1) { rowlist = g_rows_edge;  wlist = g_w_edge;  cap = CAPE; }
    else                 { rowlist = g_rows_angle; wlist = g_w_angle; cap = CAPA; }

    int i = blockIdx.x * blockDim.x + threadIdx.x;
    if (i >= M) return;
    int src = (WHICH == 0) ? i : map[i];
    int lane = threadIdx.x & 31;

#pragma unroll
    for (int k = 0; k < 2; ++k) {
        int   e = idx[2 * src + k];
        float w = wts[2 * src + k];
        unsigned mask = __match_any_sync(0xffffffffu, e);
        int leader = __ffs(mask) - 1;
        int rank   = __popc(mask & ((1u << lane) - 1u));
        int base = 0;
        if (lane == leader) base = atomicAdd(&cnt[e], __popc(mask));
        base = __shfl_sync(mask, base, leader);
        int p = base + rank;
        if (p > cap - 1) p = cap - 1;     // statistically impossible; keep in bounds
        int flat = e * cap + p;
        rowlist[flat] = i;
        wlist[flat]   = w;
    }
}

// ---------------- grouped HMMA GEMM -----------------------------------------
// 64 rows x full DOUT per CTA, 256 threads = 8 warps (2m x 4n), BK=32.
// K-major smem, 80B rows (conflict-free ldmatrix). A loaded fp32 (gathered
// once per slot) and converted fp16 during the fill; register prefetch
// overlaps next chunk's LDGs with current MMAs. Epilogue: bias + silu +
// topk-weight, fp32 atomicAdd directly into the pre-zeroed output.
template<int WHICH>
__global__ void __launch_bounds__(256)
moe_gemm_mma(const float* __restrict__ X, const float* __restrict__ Bias,
             float* __restrict__ Out) {
    constexpr int DIN  = (WHICH == 0) ? ND : (WHICH == 1) ? NSYM : (WHICH == 2) ? EINFO : ADIM;
    constexpr int DOUT = (WHICH <= 1) ? DO_NODE : (WHICH == 2) ? DO_EDGE : DO_ANGLE;
    constexpr int CAP  = (WHICH <= 1) ? CAPN : (WHICH == 2) ? CAPE : CAPA;
    constexpr int WN   = DOUT / 4;       // cols per warp band
    constexpr int FN   = WN / 8;         // n fragments per warp (4/6/3)
    constexpr int NCH  = DIN / 32;

    const __half* Wt;
    const int* rowlist; const float* wlist;
    if (WHICH == 0) { Wt = g_w1t; rowlist = g_rows_node;  wlist = g_w_node;  }
    if (WHICH == 1) { Wt = g_w2t; rowlist = g_rows_node;  wlist = g_w_node;  }
    if (WHICH == 2) { Wt = g_wet; rowlist = g_rows_edge;  wlist = g_w_edge;  }
    if (WHICH == 3) { Wt = g_wat; rowlist = g_rows_angle; wlist = g_w_angle; }
    const int which_r = (WHICH <= 1) ? 0 : (WHICH - 1);

    const int e = blockIdx.y;
    int count = min(g_cnt[which_r * 8 + e], CAP);
    const int m0 = blockIdx.x * 64;
    if (m0 >= count) return;

    __shared__ __align__(16) __half As[64 * 40];     // 64 rows x 80B
    __shared__ __align__(16) __half Bs[DOUT * 40];   // DOUT rows x 80B
    __shared__ int   srow[64];
    __shared__ float swt[64];

    const int tid  = threadIdx.x;
    const int wid  = tid >> 5;
    const int lane = tid & 31;
    const int warp_m = wid & 1;        // 0..1 -> 32-row band
    const int warp_n = wid >> 1;       // 0..3 -> WN-col band

    if (tid < 64) {
        int m = m0 + tid;
        if (m < count) { srow[tid] = rowlist[e * CAP + m]; swt[tid] = wlist[e * CAP + m]; }
        else           { srow[tid] = rowlist[e * CAP];     swt[tid] = 0.f; }
    }
    __syncthreads();

    // A fill: 4 threads per row, 8 fp32 each per 32-chunk
    const int arow = tid >> 2;          // 0..63
    const int aseg = tid & 3;           // 8-float segment
    const float* aptr = X + (size_t)srow[arow] * DIN + aseg * 8;
    const bool bval = tid < DOUT;
    const __half* bptr = Wt + ((size_t)e * DOUT + (bval ? tid : 0)) * DIN;

    const uint32_t As_u = smem_u32(As), Bs_u = smem_u32(Bs);
    const uint32_t a_st = As_u + (uint32_t)arow * 80u + (uint32_t)aseg * 16u;
    const uint32_t b_st = Bs_u + (uint32_t)tid * 80u;
    const uint32_t a_ld = As_u + (uint32_t)(warp_m * 32 + (lane & 15)) * 80u
                          + (uint32_t)(lane >> 4) * 16u;
    const uint32_t b_ld = Bs_u + (uint32_t)(warp_n * WN + (lane & 7)) * 80u
                          + (uint32_t)((lane >> 3) & 1) * 16u;

    float acc[2][FN][4];
#pragma unroll
    for (int i = 0; i < 2; ++i)
#pragma unroll
        for (int j = 0; j < FN; ++j)
#pragma unroll
            for (int q = 0; q < 4; ++q) acc[i][j][q] = 0.f;

    float4 ar[2];
    uint4  br[4];

    // prologue prefetch (chunk 0)
    ar[0] = *reinterpret_cast<const float4*>(aptr);
    ar[1] = *reinterpret_cast<const float4*>(aptr + 4);
    if (bval) {
#pragma unroll
        for (int j = 0; j < 4; ++j) br[j] = *reinterpret_cast<const uint4*>(bptr + j * 8);
    }

    for (int c = 0; c < NCH; ++c) {
        __syncthreads();    // previous chunk's ldmatrix reads complete
        {
            uint32_t u0 = h2b(__floats2half2_rn(ar[0].x, ar[0].y));
            uint32_t u1 = h2b(__floats2half2_rn(ar[0].z, ar[0].w));
            uint32_t u2 = h2b(__floats2half2_rn(ar[1].x, ar[1].y));
            uint32_t u3 = h2b(__floats2half2_rn(ar[1].z, ar[1].w));
            STS128(a_st, u0, u1, u2, u3);
        }
        if (bval) {
#pragma unroll
            for (int j = 0; j < 4; ++j)
                STS128(b_st + (uint32_t)j * 16u, br[j].x, br[j].y, br[j].z, br[j].w);
        }
        __syncthreads();
        // prefetch next chunk (LDG latency overlaps MMA below)
        if (c + 1 < NCH) {
            ar[0] = *reinterpret_cast<const float4*>(aptr + (c + 1) * 32);
            ar[1] = *reinterpret_cast<const float4*>(aptr + (c + 1) * 32 + 4);
            if (bval) {
#pragma unroll
                for (int j = 0; j < 4; ++j)
                    br[j] = *reinterpret_cast<const uint4*>(bptr + (c + 1) * 32 + j * 8);
            }
        }
#pragma unroll
        for (int kk = 0; kk < 2; ++kk) {
            uint32_t a[2][4], b[FN][2];
#pragma unroll
            for (int fm = 0; fm < 2; ++fm)
                LDMATRIX_X4(a[fm][0], a[fm][1], a[fm][2], a[fm][3],
                            a_ld + (uint32_t)fm * 16u * 80u + (uint32_t)kk * 32u);
#pragma unroll
            for (int fn = 0; fn < FN; ++fn)
                LDMATRIX_X2(b[fn][0], b[fn][1],
                            b_ld + (uint32_t)fn * 8u * 80u + (uint32_t)kk * 32u);
#pragma unroll
            for (int fm = 0; fm < 2; ++fm)
#pragma unroll
                for (int fn = 0; fn < FN; ++fn)
                    MMA_16816(acc[fm][fn], a[fm], b[fn]);
        }
    }

    // epilogue: bias + silu + topk-weight -> fp32 atomicAdd into output
    const int qrow = lane >> 2;
    const int qcol = (lane & 3) * 2;
    const float* be = Bias + e * DOUT;
#pragma unroll
    for (int fm = 0; fm < 2; ++fm) {
#pragma unroll
        for (int hf = 0; hf < 2; ++hf) {
            int rloc = warp_m * 32 + fm * 16 + hf * 8 + qrow;
            int m = m0 + rloc;
            if (m >= count) continue;
            float wt = swt[rloc];
            float* orow = Out + (size_t)srow[rloc] * DOUT;
#pragma unroll
            for (int fn = 0; fn < FN; ++fn) {
                int col = warp_n * WN + fn * 8 + qcol;
                float h0 = acc[fm][fn][hf * 2 + 0] + be[col];
                float h1 = acc[fm][fn][hf * 2 + 1] + be[col + 1];
                atomicAdd(orow + col,     wt * (h0 / (1.f + __expf(-h0))));
                atomicAdd(orow + col + 1, wt * (h1 / (1.f + __expf(-h1))));
            }
        }
    }
}

// ---------------- launch ----------------------------------------------------
extern "C" void kernel_launch(void* const* d_in, const int* in_sizes, int n_in,
                              void* d_out, int out_size) {
    const float* x_m1 = (const float*)d_in[0];
    const float* x_m2 = (const float*)d_in[1];
    const float* x_e  = (const float*)d_in[2];
    const float* x_a  = (const float*)d_in[3];
    const float* nw   = (const float*)d_in[4];
    const int*   ni   = (const int*)  d_in[5];
    const float* ewn  = (const float*)d_in[6];
    const int*   ein  = (const int*)  d_in[7];
    const float* awn  = (const float*)d_in[8];
    const int*   ain  = (const int*)  d_in[9];
    const int*   n2e  = (const int*)  d_in[10];
    const int*   n2a  = (const int*)  d_in[11];
    const float* W1 = (const float*)d_in[12];
    const float* b1 = (const float*)d_in[13];
    const float* W2 = (const float*)d_in[14];
    const float* b2 = (const float*)d_in[15];
    const float* We = (const float*)d_in[16];
    const float* be = (const float*)d_in[17];
    const float* Wa = (const float*)d_in[18];
    const float* ba = (const float*)d_in[19];
    float* out = (float*)d_out;
    (void)in_sizes; (void)n_in; (void)out_size;

    // 1) zero output + counters; weight transpose/convert
    int n4 = (int)(OUT_TOTAL / 4);
    init_kernel<<<(n4 + 255) / 256, 256>>>(out, n4);
    wcvt_kernel<0><<<dim3((ND   / 32) * (DO_NODE  / 32), 8), dim3(32, 8)>>>(W1);
    wcvt_kernel<1><<<dim3((NSYM / 32) * (DO_NODE  / 32), 8), dim3(32, 8)>>>(W2);
    wcvt_kernel<2><<<dim3((EINFO/ 32) * (DO_EDGE  / 32), 8), dim3(32, 8)>>>(We);
    wcvt_kernel<3><<<dim3((ADIM / 32) * (DO_ANGLE / 32), 8), dim3(32, 8)>>>(Wa);

    // 2) routing
    route_kernel<0><<<N_NODE  / 256, 256>>>(ni,  nw,  nullptr, N_NODE);
    route_kernel<1><<<N_EDGE  / 256, 256>>>(ein, ewn, n2e,     N_EDGE);
    route_kernel<2><<<N_ANGLE / 256, 256>>>(ain, awn, n2a,     N_ANGLE);

    // 3) grouped HMMA GEMMs (BM=64 x full DOUT; y = expert), largest first
    moe_gemm_mma<3><<<dim3(CAPA / 64, 8), 256>>>(x_a,  ba, out + OUT_ANGLE);
    moe_gemm_mma<2><<<dim3(CAPE / 64, 8), 256>>>(x_e,  be, out + OUT_EDGE);
    moe_gemm_mma<1><<<dim3(CAPN / 64, 8), 256>>>(x_m2, b2, out + OUT_M2);
    moe_gemm_mma<0><<<dim3(CAPN / 64, 8), 256>>>(x_m1, b1, out + OUT_M1);
}